// round 10
// baseline (speedup 1.0000x reference)
#include <cuda_runtime.h>
#include <cstdint>
#include <cstddef>

#define TT 1024
#define II 64
#define HH 128
#define NCTA 128

typedef unsigned long long u64;

// ---- loop-kernel smem layout (bytes) ----
#define OFF_WS  0         // [26][512][16B] W_hh k=24..127 quad-groups
#define OFF_G   212992    // float [4][512] gate pre-activations
#define OFF_H   221184    // float [4][128] hidden state
#define OFF_WEF 223232    // float [128]
#define OFF_BE  223744    // float [4]
#define SMEM_BYTES 223760

// xp scratch: [b][t][g] fp32 -> 512*1024*512 floats = 1 GB (device-global scratch)
__device__ float g_xp[(size_t)512 * TT * 512];

__device__ __forceinline__ u64 fma2(u64 a, u64 b, u64 c) {
    u64 d;
    asm("fma.rn.f32x2 %0, %1, %2, %3;" : "=l"(d) : "l"(a), "l"(b), "l"(c));
    return d;
}
__device__ __forceinline__ void lds_v2(uint32_t a, u64& v0, u64& v1) {
    asm volatile("ld.shared.v2.u64 {%0,%1}, [%2];" : "=l"(v0), "=l"(v1) : "r"(a));
}
__device__ __forceinline__ float2 unpack2(u64 v) {
    float2 r;
    asm("mov.b64 {%0,%1}, %2;" : "=f"(r.x), "=f"(r.y) : "l"(v));
    return r;
}
__device__ __forceinline__ u64 pack2(float lo, float hi) {
    u64 v;
    asm("mov.b64 %0, {%1,%2};" : "=l"(v) : "f"(lo), "f"(hi));
    return v;
}
__device__ __forceinline__ float sigmoid_f(float x) {
    return __fdividef(1.0f, 1.0f + __expf(-x));
}
__device__ __forceinline__ float tanh_f(float x) {
    return __fdividef(2.0f, 1.0f + __expf(-2.0f * x)) - 1.0f;
}

// ================= prologue: xp[b][s][g] = x[b][s][:] . W_ih[g][:] =================
// grid 4096: bb = bx & 127 (4 batch rows), sb = bx >> 7 (32 timesteps). 512 threads = g.
__global__ void __launch_bounds__(512)
xproj_kernel(const float* __restrict__ x, const float* __restrict__ W_ih)
{
    __shared__ float xt[4 * 32 * II];   // 32 KB
    const int t  = threadIdx.x;
    const int bb = blockIdx.x & 127;
    const int sb = blockIdx.x >> 7;

    // stage x tile: 4 rows x (32 steps * 64) contiguous floats each
    #pragma unroll
    for (int i = 0; i < 4; ++i) {
        const float4* src = reinterpret_cast<const float4*>(
            x + ((size_t)(bb * 4 + i) * TT + sb * 32) * II);
        reinterpret_cast<float4*>(xt)[i * 512 + t] = src[t];
    }

    u64 w[32];
    {
        const u64* p = reinterpret_cast<const u64*>(W_ih + t * II);
        #pragma unroll
        for (int q = 0; q < 32; ++q) w[q] = p[q];
    }
    __syncthreads();

    const uint32_t sx = (uint32_t)__cvta_generic_to_shared(xt);
    #pragma unroll 2
    for (int pr = 0; pr < 128; ++pr) {
        const int i = pr >> 5, s = pr & 31;
        const uint32_t base = sx + (i * 2048 + s * II) * 4;
        u64 acc = 0ull;
        #pragma unroll
        for (int q = 0; q < 16; ++q) {
            u64 a, b;
            lds_v2(base + q * 16, a, b);
            acc = fma2(w[2 * q], a, acc);
            acc = fma2(w[2 * q + 1], b, acc);
        }
        float2 f = unpack2(acc);
        g_xp[((size_t)(bb * 4 + i) * TT + sb * 32 + s) * 512 + t] = f.x + f.y;
    }
}

// ================= sequential LSTM loop: 128 CTAs x 1024 threads =================
// thread: col = t&511 (gate column), rh = t>>9 (row half -> rows 2rh, 2rh+1)
__global__ void __launch_bounds__(1024, 1)
lstm_loop_kernel(const float* __restrict__ W_hh,
                 const float* __restrict__ b_ih, const float* __restrict__ b_hh,
                 const float* __restrict__ W1, const float* __restrict__ b1,
                 const float* __restrict__ W2, const float* __restrict__ b2,
                 float* __restrict__ out)
{
    extern __shared__ char smem[];
    const int t   = threadIdx.x;
    const int col = t & 511;
    const int rh  = t >> 9;
    const int r0  = blockIdx.x * 4;
    const uint32_t sb = (uint32_t)__cvta_generic_to_shared(smem);

    // registers: W_hh[col][0..23] as 12 u64 pairs
    u64 wr[12];
    {
        const u64* p = reinterpret_cast<const u64*>(W_hh + col * HH);
        #pragma unroll
        for (int q = 0; q < 12; ++q) wr[q] = p[q];
    }
    const float biasv = b_ih[col] + b_hh[col];

    // smem weights: groups p=0..25 hold k = 24+4p .. 27+4p, layout [p][col][16B]
    {
        const float4* ph = reinterpret_cast<const float4*>(W_hh + col * HH + 24);
        #pragma unroll
        for (int p = rh * 13; p < rh * 13 + 13; ++p)
            *reinterpret_cast<float4*>(smem + OFF_WS + p * 8192 + col * 16) = ph[p];
    }

    float* gs   = reinterpret_cast<float*>(smem + OFF_G);
    float* hs   = reinterpret_cast<float*>(smem + OFF_H);
    float* weff = reinterpret_cast<float*>(smem + OFF_WEF);
    float* beff = reinterpret_cast<float*>(smem + OFF_BE);

    if (t < 512) hs[t] = 0.0f;
    if (t >= 512 && t < 640) {            // weff on the otherwise-light half
        float s = 0.0f;
        for (int m = 0; m < 256; ++m) s += W2[m] * W1[m * HH + (t - 512)];
        weff[t - 512] = s;
    }
    if (t == 640) {
        float s = b2[0];
        for (int m = 0; m < 256; ++m) s += W2[m] * b1[m];
        beff[0] = s;
    }

    const float* xp0 = g_xp + ((size_t)(r0 + 2 * rh) * TT) * 512 + col;
    const float* xp1 = xp0 + (size_t)TT * 512;

    const uint32_t aWS = sb + OFF_WS + col * 16;
    const uint32_t aH0 = sb + OFF_H + (2 * rh) * 512;
    const uint32_t aH1 = aH0 + 512;

    float cval = 0.0f;                    // phase-B state (t<512): row t>>7, col t&127
    const int br = (t >> 7) & 3, bj = t & 127;

    float xv0 = __ldg(xp0), xv1 = __ldg(xp1);
    __syncthreads();

    #pragma unroll 1
    for (int s = 0; s < TT; ++s) {
        // prefetch xp for s+1
        float xn0 = 0.f, xn1 = 0.f;
        if (s + 1 < TT) { xn0 = __ldg(xp0 + (s + 1) * 512); xn1 = __ldg(xp1 + (s + 1) * 512); }

        u64 a0 = pack2(xv0, 0.0f);
        u64 a1 = pack2(xv1, 0.0f);

        // k = 0..23 from register weights
        #pragma unroll
        for (int q = 0; q < 6; ++q) {
            u64 p0, p1, p2, p3;
            lds_v2(aH0 + q * 16, p0, p1);
            lds_v2(aH1 + q * 16, p2, p3);
            a0 = fma2(wr[2 * q], p0, a0);  a0 = fma2(wr[2 * q + 1], p1, a0);
            a1 = fma2(wr[2 * q], p2, a1);  a1 = fma2(wr[2 * q + 1], p3, a1);
        }
        // k = 24..127 from smem weights
        #pragma unroll
        for (int p = 0; p < 26; ++p) {
            u64 w0, w1, p0, p1, p2, p3;
            lds_v2(aWS + p * 8192, w0, w1);
            lds_v2(aH0 + 96 + p * 16, p0, p1);
            lds_v2(aH1 + 96 + p * 16, p2, p3);
            a0 = fma2(w0, p0, a0);  a0 = fma2(w1, p1, a0);
            a1 = fma2(w0, p2, a1);  a1 = fma2(w1, p3, a1);
        }

        float2 f0 = unpack2(a0), f1 = unpack2(a1);
        gs[(2 * rh) * 512 + col] = (f0.x + f0.y) + biasv;
        gs[(2 * rh + 1) * 512 + col] = (f1.x + f1.y) + biasv;
        xv0 = xn0; xv1 = xn1;
        __syncthreads();

        if (t < 512) {
            float gi = gs[br * 512 + bj];
            float gf = gs[br * 512 + 128 + bj];
            float gg = gs[br * 512 + 256 + bj];
            float go = gs[br * 512 + 384 + bj];
            cval = sigmoid_f(gf) * cval + sigmoid_f(gi) * tanh_f(gg);
            hs[br * HH + bj] = sigmoid_f(go) * tanh_f(cval);
        }
        __syncthreads();
    }

    if (t < 4) {
        float s = beff[0];
        #pragma unroll 8
        for (int j = 0; j < HH; ++j) s += hs[t * HH + j] * weff[j];
        out[r0 + t] = s;
    }
}

extern "C" void kernel_launch(void* const* d_in, const int* in_sizes, int n_in,
                              void* d_out, int out_size) {
    const float* x    = (const float*)d_in[0];
    const float* W_ih = (const float*)d_in[1];
    const float* W_hh = (const float*)d_in[2];
    const float* b_ih = (const float*)d_in[3];
    const float* b_hh = (const float*)d_in[4];
    const float* W1   = (const float*)d_in[5];
    const float* b1   = (const float*)d_in[6];
    const float* W2   = (const float*)d_in[7];
    const float* b2   = (const float*)d_in[8];
    float* out = (float*)d_out;

    cudaFuncSetAttribute(lstm_loop_kernel,
                         cudaFuncAttributeMaxDynamicSharedMemorySize, SMEM_BYTES);

    xproj_kernel<<<4096, 512>>>(x, W_ih);
    lstm_loop_kernel<<<NCTA, 1024, SMEM_BYTES>>>(W_hh, b_ih, b_hh, W1, b1, W2, b2, out);
}

// round 11
// speedup vs baseline: 1.3467x; 1.3467x over previous
#include <cuda_runtime.h>
#include <cstdint>
#include <cstddef>

#define TT 1024
#define II 64
#define HH 128
#define NCTA 128

typedef unsigned long long u64;

// ---- loop-kernel smem layout (bytes) ----
// weights: [11 slots][4 kq][256 colidx] x 16B ; slot stride = 4*256*16 = 16384
#define OFF_WS  0
#define OFF_GS  180224   // float [4 kq][4 r][512 col] partial gate sums (32 KB)
#define OFF_H   212992   // float [4][128] hidden state
#define OFF_WEF 215040   // float [128]
#define OFF_BE  215552   // float [4]
#define SMEM_BYTES 215568

// xp scratch: [b][t][g] fp32 (+pad so the s+1 prefetch at the last step is safe)
__device__ float g_xp[(size_t)512 * TT * 512 + 1024];

__device__ __forceinline__ u64 fma2(u64 a, u64 b, u64 c) {
    u64 d;
    asm("fma.rn.f32x2 %0, %1, %2, %3;" : "=l"(d) : "l"(a), "l"(b), "l"(c));
    return d;
}
__device__ __forceinline__ void lds_v2(uint32_t a, u64& v0, u64& v1) {
    asm volatile("ld.shared.v2.u64 {%0,%1}, [%2];" : "=l"(v0), "=l"(v1) : "r"(a));
}
__device__ __forceinline__ float2 unpack2(u64 v) {
    float2 r;
    asm("mov.b64 {%0,%1}, %2;" : "=f"(r.x), "=f"(r.y) : "l"(v));
    return r;
}
__device__ __forceinline__ float sigmoid_f(float x) {
    return __fdividef(1.0f, 1.0f + __expf(-x));
}
__device__ __forceinline__ float tanh_f(float x) {
    return __fdividef(2.0f, 1.0f + __expf(-2.0f * x)) - 1.0f;
}

// ================= prologue: xp[b][s][g] = x[b][s][:] . W_ih[g][:] =================
// grid 4096: bb = bx & 127 (4 batch rows), sb = bx >> 7 (32 timesteps). 512 threads = gate g.
__global__ void __launch_bounds__(512, 1)
xproj_kernel(const float* __restrict__ x, const float* __restrict__ W_ih)
{
    __shared__ float xt[4 * 32 * II];   // 32 KB
    const int t  = threadIdx.x;
    const int bb = blockIdx.x & 127;
    const int sbk = blockIdx.x >> 7;

    // stage x tile: 4 rows x (32 steps * 64) contiguous floats each
    #pragma unroll
    for (int i = 0; i < 4; ++i) {
        const float4* src = reinterpret_cast<const float4*>(
            x + ((size_t)(bb * 4 + i) * TT + sbk * 32) * II);
        reinterpret_cast<float4*>(xt)[i * 512 + t] = src[t];
    }

    u64 w[32];
    {
        const u64* p = reinterpret_cast<const u64*>(W_ih + t * II);
        #pragma unroll
        for (int q = 0; q < 32; ++q) w[q] = p[q];
    }
    __syncthreads();

    const uint32_t sx = (uint32_t)__cvta_generic_to_shared(xt);
    #pragma unroll 1
    for (int i = 0; i < 4; ++i) {
        const uint32_t bi = sx + i * 8192;
        float* dst = &g_xp[((size_t)(bb * 4 + i) * TT + sbk * 32) * 512 + t];
        #pragma unroll 4
        for (int s = 0; s < 32; ++s) {
            const uint32_t ba = bi + s * 256;
            u64 accA = 0ull, accB = 0ull;   // two independent k-chains
            #pragma unroll
            for (int q = 0; q < 8; ++q) {
                u64 a, b, c, d;
                lds_v2(ba + q * 16, a, b);
                lds_v2(ba + 128 + q * 16, c, d);
                accA = fma2(w[2 * q], a, accA);
                accA = fma2(w[2 * q + 1], b, accA);
                accB = fma2(w[16 + 2 * q], c, accB);
                accB = fma2(w[16 + 2 * q + 1], d, accB);
            }
            float2 fa = unpack2(accA), fb = unpack2(accB);
            dst[(size_t)s * 512] = (fa.x + fa.y) + (fb.x + fb.y);
        }
    }
}

// ================= sequential LSTM loop: 128 CTAs x 1024 threads =================
// thread: colidx = t&255 -> gate columns (colidx, colidx+256); kq = t>>8 -> k in [32kq, 32kq+32)
__global__ void __launch_bounds__(1024, 1)
lstm_loop_kernel(const float* __restrict__ W_hh,
                 const float* __restrict__ b_ih, const float* __restrict__ b_hh,
                 const float* __restrict__ W1, const float* __restrict__ b1,
                 const float* __restrict__ W2, const float* __restrict__ b2,
                 float* __restrict__ out)
{
    extern __shared__ char smem[];
    const int t      = threadIdx.x;
    const int colidx = t & 255;
    const int kq     = t >> 8;
    const int kb     = kq * 32;
    const int c0     = colidx;
    const int c1     = colidx + 256;
    const int r0     = blockIdx.x * 4;
    const uint32_t sb = (uint32_t)__cvta_generic_to_shared(smem);

    // register weights: W_hh[c0][kb .. kb+19] as 10 u64 pairs
    u64 wA[10];
    {
        const u64* p = reinterpret_cast<const u64*>(W_hh + c0 * HH + kb);
        #pragma unroll
        for (int q = 0; q < 10; ++q) wA[q] = p[q];
    }

    // smem weights: slots 0..2 = c0 k kb+20..kb+31 ; slots 3..10 = c1 k kb..kb+31
    {
        const float4* pa = reinterpret_cast<const float4*>(W_hh + c0 * HH + kb + 20);
        #pragma unroll
        for (int s2 = 0; s2 < 3; ++s2)
            *reinterpret_cast<float4*>(smem + OFF_WS + ((s2 * 4 + kq) * 256 + colidx) * 16) = pa[s2];
        const float4* pb = reinterpret_cast<const float4*>(W_hh + c1 * HH + kb);
        #pragma unroll
        for (int s2 = 0; s2 < 8; ++s2)
            *reinterpret_cast<float4*>(smem + OFF_WS + (((s2 + 3) * 4 + kq) * 256 + colidx) * 16) = pb[s2];
    }

    float* gs   = reinterpret_cast<float*>(smem + OFF_GS);
    float* hs   = reinterpret_cast<float*>(smem + OFF_H);
    float* weff = reinterpret_cast<float*>(smem + OFF_WEF);
    float* beff = reinterpret_cast<float*>(smem + OFF_BE);

    if (t < 512) hs[t] = 0.0f;
    if (t >= 512 && t < 640) {
        float s = 0.0f;
        for (int m = 0; m < 256; ++m) s += W2[m] * W1[m * HH + (t - 512)];
        weff[t - 512] = s;
    }
    if (t == 640) {
        float s = b2[0];
        for (int m = 0; m < 256; ++m) s += W2[m] * b1[m];
        beff[0] = s;
    }

    // ---- phase-B per-thread state (threads 0..511): row br, h-column bj ----
    const int br = (t >> 7) & 3;
    const int bj = t & 127;
    float biasI = 0.f, biasF = 0.f, biasG = 0.f, biasO = 0.f;
    const float* xpp = g_xp + ((size_t)(r0 + br) * TT) * 512 + bj;
    float xv0 = 0.f, xv1 = 0.f, xv2 = 0.f, xv3 = 0.f;
    float cval = 0.0f;
    if (t < 512) {
        biasI = b_ih[bj]            + b_hh[bj];
        biasF = b_ih[HH + bj]       + b_hh[HH + bj];
        biasG = b_ih[2 * HH + bj]   + b_hh[2 * HH + bj];
        biasO = b_ih[3 * HH + bj]   + b_hh[3 * HH + bj];
        xv0 = __ldg(xpp);
        xv1 = __ldg(xpp + 128);
        xv2 = __ldg(xpp + 256);
        xv3 = __ldg(xpp + 384);
    }

    const uint32_t aW = sb + OFF_WS + (kq * 256 + colidx) * 16;
    const uint32_t aH = sb + OFF_H + kb * 4;

    __syncthreads();

    #pragma unroll 1
    for (int s = 0; s < TT; ++s) {
        // ---------------- phase A: partial gate sums over this thread's 32 k ----------------
        u64 a0r0 = 0ull, a0r1 = 0ull, a0r2 = 0ull, a0r3 = 0ull;
        u64 a1r0 = 0ull, a1r1 = 0ull, a1r2 = 0ull, a1r3 = 0ull;

        #pragma unroll
        for (int g = 0; g < 8; ++g) {
            u64 wb0, wb1;
            lds_v2(aW + (3 + g) * 16384, wb0, wb1);        // c1 weights
            u64 wa0, wa1;
            if (g < 5) { wa0 = wA[2 * g]; wa1 = wA[2 * g + 1]; }
            else       { lds_v2(aW + (g - 5) * 16384, wa0, wa1); }

            u64 p0, p1;
            lds_v2(aH + 0 * 512 + g * 16, p0, p1);
            a0r0 = fma2(wa0, p0, a0r0);  a0r0 = fma2(wa1, p1, a0r0);
            a1r0 = fma2(wb0, p0, a1r0);  a1r0 = fma2(wb1, p1, a1r0);
            lds_v2(aH + 1 * 512 + g * 16, p0, p1);
            a0r1 = fma2(wa0, p0, a0r1);  a0r1 = fma2(wa1, p1, a0r1);
            a1r1 = fma2(wb0, p0, a1r1);  a1r1 = fma2(wb1, p1, a1r1);
            lds_v2(aH + 2 * 512 + g * 16, p0, p1);
            a0r2 = fma2(wa0, p0, a0r2);  a0r2 = fma2(wa1, p1, a0r2);
            a1r2 = fma2(wb0, p0, a1r2);  a1r2 = fma2(wb1, p1, a1r2);
            lds_v2(aH + 3 * 512 + g * 16, p0, p1);
            a0r3 = fma2(wa0, p0, a0r3);  a0r3 = fma2(wa1, p1, a0r3);
            a1r3 = fma2(wb0, p0, a1r3);  a1r3 = fma2(wb1, p1, a1r3);
        }

        {
            float2 f;
            f = unpack2(a0r0); gs[(kq * 4 + 0) * 512 + c0] = f.x + f.y;
            f = unpack2(a0r1); gs[(kq * 4 + 1) * 512 + c0] = f.x + f.y;
            f = unpack2(a0r2); gs[(kq * 4 + 2) * 512 + c0] = f.x + f.y;
            f = unpack2(a0r3); gs[(kq * 4 + 3) * 512 + c0] = f.x + f.y;
            f = unpack2(a1r0); gs[(kq * 4 + 0) * 512 + c1] = f.x + f.y;
            f = unpack2(a1r1); gs[(kq * 4 + 1) * 512 + c1] = f.x + f.y;
            f = unpack2(a1r2); gs[(kq * 4 + 2) * 512 + c1] = f.x + f.y;
            f = unpack2(a1r3); gs[(kq * 4 + 3) * 512 + c1] = f.x + f.y;
        }
        __syncthreads();

        // ---------------- phase B: reduce partials, activations, state update ----------------
        if (t < 512) {
            // prefetch xp for step s+1 (pad in g_xp covers the final step)
            const float* xn = xpp + (size_t)(s + 1) * 512;
            float xn0 = __ldg(xn), xn1 = __ldg(xn + 128), xn2 = __ldg(xn + 256), xn3 = __ldg(xn + 384);

            float pi = xv0 + biasI, pf = xv1 + biasF, pg = xv2 + biasG, po = xv3 + biasO;
            #pragma unroll
            for (int q = 0; q < 4; ++q) {
                const int base = (q * 4 + br) * 512 + bj;
                pi += gs[base];
                pf += gs[base + 128];
                pg += gs[base + 256];
                po += gs[base + 384];
            }
            float ig = sigmoid_f(pi);
            float fg = sigmoid_f(pf);
            float gv = tanh_f(pg);
            float og = sigmoid_f(po);
            cval = fg * cval + ig * gv;
            hs[br * HH + bj] = og * tanh_f(cval);
            xv0 = xn0; xv1 = xn1; xv2 = xn2; xv3 = xn3;
        }
        __syncthreads();
    }

    // ---------------- fused fc1+fc2 epilogue ----------------
    if (t < 4) {
        float s = beff[0];
        #pragma unroll 8
        for (int j = 0; j < HH; ++j) s += hs[t * HH + j] * weff[j];
        out[r0 + t] = s;
    }
}

extern "C" void kernel_launch(void* const* d_in, const int* in_sizes, int n_in,
                              void* d_out, int out_size) {
    const float* x    = (const float*)d_in[0];
    const float* W_ih = (const float*)d_in[1];
    const float* W_hh = (const float*)d_in[2];
    const float* b_ih = (const float*)d_in[3];
    const float* b_hh = (const float*)d_in[4];
    const float* W1   = (const float*)d_in[5];
    const float* b1   = (const float*)d_in[6];
    const float* W2   = (const float*)d_in[7];
    const float* b2   = (const float*)d_in[8];
    float* out = (float*)d_out;

    cudaFuncSetAttribute(lstm_loop_kernel,
                         cudaFuncAttributeMaxDynamicSharedMemorySize, SMEM_BYTES);

    xproj_kernel<<<4096, 512>>>(x, W_ih);
    lstm_loop_kernel<<<NCTA, 1024, SMEM_BYTES>>>(W_hh, b_ih, b_hh, W1, b1, W2, b2, out);
}